// round 4
// baseline (speedup 1.0000x reference)
#include <cuda_runtime.h>
#include <cuda_bf16.h>
#include <cstdint>
#include <cstddef>

#define NROWS_MAX 16384
#define DDIM 256            // K, bytes per row in fp8
#define TILE 128
#define ROWB 272            // padded smem row bytes (256 + 16) -> conflict-free
#define TILE_SMEM (TILE*ROWB)       // 34816
#define SMEM_BYTES (3*TILE_SMEM)    // A + B0 + B1 = 104448
#define NTHREADS 256

__device__ __align__(16) uint8_t g_Xq[(size_t)NROWS_MAX*DDIM];
__device__ __align__(16) uint8_t g_Yq[(size_t)NROWS_MAX*DDIM];
__device__ float  g_Sv[NROWS_MAX];
__device__ double g_acc;

static __device__ __forceinline__ uint32_t smem_u32(const void* p){
    return (uint32_t)__cvta_generic_to_shared(p);
}
static __device__ __forceinline__ void cp16(void* dst, const void* src){
    asm volatile("cp.async.cg.shared.global [%0], [%1], 16;\n"
                 :: "r"(smem_u32(dst)), "l"(src));
}
static __device__ __forceinline__ void cp_commit(){
    asm volatile("cp.async.commit_group;\n");
}
template<int N> static __device__ __forceinline__ void cp_wait(){
    asm volatile("cp.async.wait_group %0;\n" :: "n"(N));
}
static __device__ __forceinline__ float ex2f(float x){
    float r; asm("ex2.approx.ftz.f32 %0, %1;" : "=f"(r) : "f"(x)); return r;
}
// pack two floats -> two e4m3 bytes; lo byte = b operand
static __device__ __forceinline__ uint16_t cvt_e4m3x2(float hi, float lo){
    uint16_t r;
    asm("cvt.rn.satfinite.e4m3x2.f32 %0, %1, %2;" : "=h"(r) : "f"(hi), "f"(lo));
    return r;
}

// ---------------- normalize: fp32 row -> unit-norm e4m3 row (plain row-major) ------
__global__ void norm_kernel(const float* __restrict__ in, int which, int nrows){
    int gw   = (blockIdx.x*blockDim.x + threadIdx.x) >> 5;
    int lane = threadIdx.x & 31;
    if (gw >= nrows) return;
    const float4* rp = reinterpret_cast<const float4*>(in) + (size_t)gw*(DDIM/4);
    float4 v0 = rp[lane*2 + 0];
    float4 v1 = rp[lane*2 + 1];
    float ss = v0.x*v0.x + v0.y*v0.y + v0.z*v0.z + v0.w*v0.w
             + v1.x*v1.x + v1.y*v1.y + v1.z*v1.z + v1.w*v1.w;
    #pragma unroll
    for (int o=16;o;o>>=1) ss += __shfl_xor_sync(0xffffffffu, ss, o);
    float inv = 1.0f / fmaxf(sqrtf(ss), 1e-12f);
    union { uint16_t q[4]; uint2 u; } pk;
    pk.q[0] = cvt_e4m3x2(v0.y*inv, v0.x*inv);
    pk.q[1] = cvt_e4m3x2(v0.w*inv, v0.z*inv);
    pk.q[2] = cvt_e4m3x2(v1.y*inv, v1.x*inv);
    pk.q[3] = cvt_e4m3x2(v1.w*inv, v1.z*inv);
    uint8_t* out = which ? g_Yq : g_Xq;
    *reinterpret_cast<uint2*>(out + (size_t)gw*DDIM + lane*8) = pk.u;
}

// ---------------- Sv diagonal (fp32): (dot-1)/t ; zero acc ----------------
__global__ void sv_kernel(const float* __restrict__ X, const float* __restrict__ Y, int nrows){
    if (blockIdx.x==0 && threadIdx.x==0) g_acc = 0.0;
    int gw   = (blockIdx.x*blockDim.x + threadIdx.x) >> 5;
    int lane = threadIdx.x & 31;
    if (gw >= nrows) return;
    const float4* xp = reinterpret_cast<const float4*>(X) + (size_t)gw*(DDIM/4);
    const float4* yp = reinterpret_cast<const float4*>(Y) + (size_t)gw*(DDIM/4);
    float dot=0.f, ssx=0.f, ssy=0.f;
    #pragma unroll
    for (int j=0;j<2;j++){
        float4 x = xp[lane*2+j], y = yp[lane*2+j];
        dot += x.x*y.x + x.y*y.y + x.z*y.z + x.w*y.w;
        ssx += x.x*x.x + x.y*x.y + x.z*x.z + x.w*x.w;
        ssy += y.x*y.x + y.y*y.y + y.z*y.z + y.w*y.w;
    }
    #pragma unroll
    for (int o=16;o;o>>=1){
        dot += __shfl_xor_sync(0xffffffffu, dot, o);
        ssx += __shfl_xor_sync(0xffffffffu, ssx, o);
        ssy += __shfl_xor_sync(0xffffffffu, ssy, o);
    }
    if (lane==0){
        float d = dot / (fmaxf(sqrtf(ssx),1e-12f) * fmaxf(sqrtf(ssy),1e-12f));
        g_Sv[gw] = (d - 1.0f) * 14.285714285714286f;
    }
}

#define KC 20.609929155556602f   // log2(e)/0.07

// one B-tile iteration: prefetch it+1, fp8 MMA for tile it into accC,
// interleaved exp-epilogue of tile it-1 from accP.
static __device__ __forceinline__ void tile_body(
    int it, int nT, char* sm, float (&accC)[64], float (&accP)[64],
    float (&rowsum)[4], int tid, int wm, int wn, int g, int t)
{
    char* buf0 = sm + TILE_SMEM;
    char* buf1 = sm + 2*TILE_SMEM;

    if (it+1 < nT){
        char* bw = ((it+1)&1) ? buf1 : buf0;
        const uint8_t* src = g_Yq + (size_t)(it+1)*TILE*DDIM;
        #pragma unroll
        for (int j=0;j<8;j++){
            int idx = tid + NTHREADS*j;          // 2048 16B chunks
            int r = idx >> 4, c = idx & 15;
            cp16(bw + r*ROWB + c*16, src + r*DDIM + c*16);
        }
        cp_commit();
        cp_wait<1>();
    } else {
        cp_wait<0>();
    }
    __syncthreads();

    const char* Bs = (it&1) ? buf1 : buf0;
    const char* Ap = sm + (wm*32 + g)*ROWB + t*4;
    const char* Bp = Bs + (wn*64 + g)*ROWB + t*4;

    #pragma unroll
    for (int ks=0; ks<8; ++ks){
        const int ko = ks*32;
        uint32_t a[2][4];
        #pragma unroll
        for (int mc=0;mc<2;mc++){
            const char* p = Ap + mc*16*ROWB + ko;
            a[mc][0] = *(const uint32_t*)(p);
            a[mc][1] = *(const uint32_t*)(p + 8*ROWB);
            a[mc][2] = *(const uint32_t*)(p + 16);
            a[mc][3] = *(const uint32_t*)(p + 8*ROWB + 16);
        }
        uint32_t b[8][2];
        #pragma unroll
        for (int nc=0;nc<8;nc++){
            const char* p = Bp + nc*8*ROWB + ko;
            b[nc][0] = *(const uint32_t*)(p);
            b[nc][1] = *(const uint32_t*)(p + 16);
        }
        #pragma unroll
        for (int mc=0;mc<2;mc++)
            #pragma unroll
            for (int nc=0;nc<8;nc++){
                float* c = &accC[(mc*8 + nc)*4];
                asm volatile(
                    "mma.sync.aligned.m16n8k32.row.col.f32.e4m3.e4m3.f32 "
                    "{%0,%1,%2,%3}, {%4,%5,%6,%7}, {%8,%9}, {%0,%1,%2,%3};\n"
                    : "+f"(c[0]),"+f"(c[1]),"+f"(c[2]),"+f"(c[3])
                    : "r"(a[mc][0]),"r"(a[mc][1]),"r"(a[mc][2]),"r"(a[mc][3]),
                      "r"(b[nc][0]),"r"(b[nc][1]));
            }
        // interleaved epilogue: 8 elements of previous tile per k-step
        #pragma unroll
        for (int e=0;e<8;e++){
            int j = ks*8 + e;
            int mc = j >> 5, i = j & 3;
            float v = accP[j];
            rowsum[mc*2 + (i>>1)] += ex2f(fmaf(v, KC, -KC));
            accP[j] = 0.f;
        }
    }
    __syncthreads();   // all reads of this B buffer done before reuse
}

// ---------------- main fused fp8 GEMM + exp + row-sum ----------------
__global__ void __launch_bounds__(NTHREADS, 1) lit_main_kernel(int nrows){
    extern __shared__ char sm[];
    __shared__ float rowsum_sm[TILE];
    __shared__ float red_sm[8];

    const int tid  = threadIdx.x;
    const int lane = tid & 31, wid = tid >> 5;
    const int wm = wid >> 1, wn = wid & 1;       // 4x2 warp grid
    const int g = lane >> 2, t = lane & 3;
    const int cta = blockIdx.x;
    const int nT = nrows / TILE;

    if (tid < TILE) rowsum_sm[tid] = 0.0f;

    // prologue: stage A tile + B tile 0 as one cp.async group
    {
        const uint8_t* Xg = g_Xq + (size_t)cta*TILE*DDIM;
        #pragma unroll
        for (int j=0;j<8;j++){
            int idx = tid + NTHREADS*j;
            int r = idx >> 4, c = idx & 15;
            cp16(sm + r*ROWB + c*16, Xg + r*DDIM + c*16);
        }
        const uint8_t* Yg = g_Yq;
        #pragma unroll
        for (int j=0;j<8;j++){
            int idx = tid + NTHREADS*j;
            int r = idx >> 4, c = idx & 15;
            cp16(sm + TILE_SMEM + r*ROWB + c*16, Yg + r*DDIM + c*16);
        }
        cp_commit();
    }

    float acc0[64], acc1[64];
    #pragma unroll
    for (int j=0;j<64;j++){ acc0[j]=0.f; acc1[j]=0.f; }
    float rowsum[4] = {0.f,0.f,0.f,0.f};

    for (int it = 0; it < nT; it += 2){
        tile_body(it,   nT, sm, acc0, acc1, rowsum, tid, wm, wn, g, t);
        tile_body(it+1, nT, sm, acc1, acc0, rowsum, tid, wm, wn, g, t);
    }
    // final epilogue: last tile (odd index) lives in acc1
    #pragma unroll
    for (int j=0;j<64;j++){
        int mc = j >> 5, i = j & 3;
        rowsum[mc*2 + (i>>1)] += ex2f(fmaf(acc1[j], KC, -KC));
    }
    // remove the 16 spurious zero-acc terms per rowsum slot from tile-0's interleave
    {
        float sp = 16.0f * ex2f(-KC);
        #pragma unroll
        for (int j=0;j<4;j++) rowsum[j] -= sp;
    }

    // reduce across the 4 lanes sharing a row
    #pragma unroll
    for (int j=0;j<4;j++){
        rowsum[j] += __shfl_xor_sync(0xffffffffu, rowsum[j], 1);
        rowsum[j] += __shfl_xor_sync(0xffffffffu, rowsum[j], 2);
    }
    if (t == 0){
        #pragma unroll
        for (int j=0;j<4;j++){
            int mc = j>>1, h = j&1;
            int r = wm*32 + mc*16 + h*8 + g;
            atomicAdd(&rowsum_sm[r], rowsum[j]);   // merge wn=0/1
        }
    }
    __syncthreads();

    float val = 0.f;
    if (tid < TILE){
        int grow = cta*TILE + tid;
        val = logf(rowsum_sm[tid]) - g_Sv[grow];
    }
    __syncthreads();
    #pragma unroll
    for (int o=16;o;o>>=1) val += __shfl_xor_sync(0xffffffffu, val, o);
    if (lane==0) red_sm[wid] = val;
    __syncthreads();
    if (tid==0){
        double s = 0.0;
        #pragma unroll
        for (int w=0;w<8;w++) s += (double)red_sm[w];
        atomicAdd(&g_acc, s);
    }
}

__global__ void finalize_kernel(float* __restrict__ out, int nrows){
    if (threadIdx.x==0 && blockIdx.x==0)
        out[0] = (float)(g_acc / (double)nrows);
}

extern "C" void kernel_launch(void* const* d_in, const int* in_sizes, int n_in,
                              void* d_out, int out_size){
    const float* X = (const float*)d_in[0];   // text_features
    const float* Y = (const float*)d_in[1];   // image_features
    float* out = (float*)d_out;
    int nrows = in_sizes[0] / DDIM;

    int nb = (nrows*32 + NTHREADS - 1) / NTHREADS;   // one warp per row
    norm_kernel<<<nb, NTHREADS>>>(X, 0, nrows);
    norm_kernel<<<nb, NTHREADS>>>(Y, 1, nrows);
    sv_kernel<<<nb, NTHREADS>>>(X, Y, nrows);

    cudaFuncSetAttribute(lit_main_kernel,
                         cudaFuncAttributeMaxDynamicSharedMemorySize, SMEM_BYTES);
    lit_main_kernel<<<nrows/TILE, NTHREADS, SMEM_BYTES>>>(nrows);

    finalize_kernel<<<1, 32>>>(out, nrows);
}

// round 5
// speedup vs baseline: 1.1194x; 1.1194x over previous
#include <cuda_runtime.h>
#include <cuda_bf16.h>
#include <cstdint>
#include <cstddef>

#define NROWS_MAX 16384
#define DDIM 256            // K bytes per row (fp8)
#define TILE 128
#define ROWB 272            // padded smem row bytes -> conflict-free LDS/ldmatrix
#define TILE_SMEM (TILE*ROWB)          // 34816
#define SMEM_BYTES (4*TILE_SMEM)       // A + B0 + B1 + B2 = 139264
#define NTHREADS 512
#define CHUNK_T 16          // B tiles per work item

__device__ __align__(16) uint8_t g_Xq[(size_t)NROWS_MAX*DDIM];
__device__ __align__(16) uint8_t g_Yq[(size_t)NROWS_MAX*DDIM];
__device__ float  g_Sv[NROWS_MAX];
__device__ float  g_rowsum[NROWS_MAX];
__device__ double g_acc;

static __device__ __forceinline__ uint32_t su32(const void* p){
    return (uint32_t)__cvta_generic_to_shared(p);
}
static __device__ __forceinline__ void cp16(uint32_t dst, const void* src){
    asm volatile("cp.async.cg.shared.global [%0], [%1], 16;\n" :: "r"(dst), "l"(src));
}
static __device__ __forceinline__ void cp_commit(){
    asm volatile("cp.async.commit_group;\n");
}
template<int N> static __device__ __forceinline__ void cp_wait(){
    asm volatile("cp.async.wait_group %0;\n" :: "n"(N));
}
static __device__ __forceinline__ float ex2f(float x){
    float r; asm("ex2.approx.ftz.f32 %0, %1;" : "=f"(r) : "f"(x)); return r;
}
static __device__ __forceinline__ uint16_t cvt_e4m3x2(float hi, float lo){
    uint16_t r;
    asm("cvt.rn.satfinite.e4m3x2.f32 %0, %1, %2;" : "=h"(r) : "f"(hi), "f"(lo));
    return r;
}
static __device__ __forceinline__ void ldsm4(uint32_t (&r)[4], uint32_t addr){
    asm volatile("ldmatrix.sync.aligned.m8n8.x4.shared.b16 {%0,%1,%2,%3}, [%4];"
        : "=r"(r[0]),"=r"(r[1]),"=r"(r[2]),"=r"(r[3]) : "r"(addr));
}
static __device__ __forceinline__ void mma_fp8(float* c, const uint32_t* a, const uint32_t* b){
    asm volatile(
        "mma.sync.aligned.m16n8k32.row.col.f32.e4m3.e4m3.f32 "
        "{%0,%1,%2,%3}, {%4,%5,%6,%7}, {%8,%9}, {%0,%1,%2,%3};\n"
        : "+f"(c[0]),"+f"(c[1]),"+f"(c[2]),"+f"(c[3])
        : "r"(a[0]),"r"(a[1]),"r"(a[2]),"r"(a[3]), "r"(b[0]),"r"(b[1]));
}

#define KC 20.609929155556602f   // log2(e)/0.07

// ---------------- normalize: fp32 row -> unit-norm e4m3 row ----------------
__global__ void norm_kernel(const float* __restrict__ in, int which, int nrows){
    int gw   = (blockIdx.x*blockDim.x + threadIdx.x) >> 5;
    int lane = threadIdx.x & 31;
    if (gw >= nrows) return;
    const float4* rp = reinterpret_cast<const float4*>(in) + (size_t)gw*(DDIM/4);
    float4 v0 = rp[lane*2 + 0];
    float4 v1 = rp[lane*2 + 1];
    float ss = v0.x*v0.x + v0.y*v0.y + v0.z*v0.z + v0.w*v0.w
             + v1.x*v1.x + v1.y*v1.y + v1.z*v1.z + v1.w*v1.w;
    #pragma unroll
    for (int o=16;o;o>>=1) ss += __shfl_xor_sync(0xffffffffu, ss, o);
    float inv = 1.0f / fmaxf(sqrtf(ss), 1e-12f);
    union { uint16_t q[4]; uint2 u; } pk;
    pk.q[0] = cvt_e4m3x2(v0.y*inv, v0.x*inv);
    pk.q[1] = cvt_e4m3x2(v0.w*inv, v0.z*inv);
    pk.q[2] = cvt_e4m3x2(v1.y*inv, v1.x*inv);
    pk.q[3] = cvt_e4m3x2(v1.w*inv, v1.z*inv);
    uint8_t* out = which ? g_Yq : g_Xq;
    *reinterpret_cast<uint2*>(out + (size_t)gw*DDIM + lane*8) = pk.u;
}

// ------------- Sv diagonal (fp32): (dot-1)/t ; zero rowsum + acc -------------
__global__ void sv_kernel(const float* __restrict__ X, const float* __restrict__ Y, int nrows){
    if (blockIdx.x==0 && threadIdx.x==0) g_acc = 0.0;
    int gw   = (blockIdx.x*blockDim.x + threadIdx.x) >> 5;
    int lane = threadIdx.x & 31;
    if (gw >= nrows) return;
    const float4* xp = reinterpret_cast<const float4*>(X) + (size_t)gw*(DDIM/4);
    const float4* yp = reinterpret_cast<const float4*>(Y) + (size_t)gw*(DDIM/4);
    float dot=0.f, ssx=0.f, ssy=0.f;
    #pragma unroll
    for (int j=0;j<2;j++){
        float4 x = xp[lane*2+j], y = yp[lane*2+j];
        dot += x.x*y.x + x.y*y.y + x.z*y.z + x.w*y.w;
        ssx += x.x*x.x + x.y*x.y + x.z*x.z + x.w*x.w;
        ssy += y.x*y.x + y.y*y.y + y.z*y.z + y.w*y.w;
    }
    #pragma unroll
    for (int o=16;o;o>>=1){
        dot += __shfl_xor_sync(0xffffffffu, dot, o);
        ssx += __shfl_xor_sync(0xffffffffu, ssx, o);
        ssy += __shfl_xor_sync(0xffffffffu, ssy, o);
    }
    if (lane==0){
        float d = dot / (fmaxf(sqrtf(ssx),1e-12f) * fmaxf(sqrtf(ssy),1e-12f));
        g_Sv[gw] = (d - 1.0f) * 14.285714285714286f;
        g_rowsum[gw] = 0.0f;
    }
}

// ---------------- main: persistent fused fp8 GEMM + exp + row-sum ----------------
__global__ void __launch_bounds__(NTHREADS, 1) lit_main_kernel(int nrows, int items, int nTrow){
    extern __shared__ char sm[];
    __shared__ float rowsum_sm[TILE];

    const int tid  = threadIdx.x;
    const int lane = tid & 31, wid = tid >> 5;
    const int wm = wid >> 2, wn = wid & 3;       // 4x4 warp grid over 128x128
    const int g = lane >> 2, t = lane & 3;

    const uint32_t sA = su32(sm);
    // per-thread ldmatrix address components
    const uint32_t aoff = sA + (uint32_t)((wm*32 + (lane & 15))*ROWB + ((lane >> 4) & 1)*16);
    const uint32_t boff = (uint32_t)((wn*32 + (lane & 7) + ((lane >> 4) & 1)*8)*ROWB
                                     + ((lane >> 3) & 1)*16);

    for (int item = blockIdx.x; item < items; item += gridDim.x){
        const int rt = item % nTrow;          // row tile
        const int ch = item / nTrow;          // col chunk
        const int c0 = ch * CHUNK_T;

        if (tid < TILE) rowsum_sm[tid] = 0.f;

        // prologue: group0 = A + B0, group1 = B1
        {
            const uint8_t* Ag  = g_Xq + (size_t)rt*TILE*DDIM;
            const uint8_t* Yg0 = g_Yq + (size_t)c0*TILE*DDIM;
            #pragma unroll
            for (int j=0;j<4;j++){
                int idx = tid + NTHREADS*j;   // 2048 16B chunks
                int r = idx >> 4, c = idx & 15;
                cp16(sA + r*ROWB + c*16,             Ag  + r*DDIM + c*16);
                cp16(sA + TILE_SMEM + r*ROWB + c*16, Yg0 + r*DDIM + c*16);
            }
            cp_commit();
            #pragma unroll
            for (int j=0;j<4;j++){
                int idx = tid + NTHREADS*j;
                int r = idx >> 4, c = idx & 15;
                cp16(sA + 2*TILE_SMEM + r*ROWB + c*16, Yg0 + TILE*DDIM + r*DDIM + c*16);
            }
            cp_commit();
        }

        float acc[32];
        #pragma unroll
        for (int j=0;j<32;j++) acc[j] = 0.f;
        float rowsum[4] = {0.f,0.f,0.f,0.f};

        for (int it = 0; it < CHUNK_T; ++it){
            if (it + 2 < CHUNK_T){
                const uint8_t* Yg = g_Yq + (size_t)(c0 + it + 2)*TILE*DDIM;
                uint32_t bw = sA + (uint32_t)((1 + (it+2)%3)*TILE_SMEM);
                #pragma unroll
                for (int j=0;j<4;j++){
                    int idx = tid + NTHREADS*j;
                    int r = idx >> 4, c = idx & 15;
                    cp16(bw + r*ROWB + c*16, Yg + r*DDIM + c*16);
                }
            }
            cp_commit();            // uniform: one group per iteration
            cp_wait<2>();           // group for tile `it` complete
            __syncthreads();

            const uint32_t bb = sA + (uint32_t)((1 + it%3)*TILE_SMEM) + boff;

            #pragma unroll
            for (int ks=0; ks<8; ++ks){
                uint32_t a0[4], a1[4], b0[4], b1[4];
                ldsm4(a0, aoff + ks*32);
                ldsm4(a1, aoff + 16*ROWB + ks*32);
                ldsm4(b0, bb + ks*32);
                ldsm4(b1, bb + 16*ROWB + ks*32);
                mma_fp8(acc + 0,  a0, b0 + 0);   // mc0 nc0
                mma_fp8(acc + 4,  a0, b0 + 2);   // mc0 nc1
                mma_fp8(acc + 8,  a0, b1 + 0);   // mc0 nc2
                mma_fp8(acc + 12, a0, b1 + 2);   // mc0 nc3
                mma_fp8(acc + 16, a1, b0 + 0);   // mc1 nc0
                mma_fp8(acc + 20, a1, b0 + 2);
                mma_fp8(acc + 24, a1, b1 + 0);
                mma_fp8(acc + 28, a1, b1 + 2);
            }

            // epilogue: exp((s-1)/t) accumulate, reset acc
            #pragma unroll
            for (int j=0;j<32;j++){
                int slot = ((j >> 4) << 1) | ((j & 3) >> 1);   // mc*2 + (i>>1)
                rowsum[slot] += ex2f(fmaf(acc[j], KC, -KC));
                acc[j] = 0.f;
            }
        }

        // merge: reduce over t lanes, then across wn warps via smem atomics
        #pragma unroll
        for (int s=0;s<4;s++){
            rowsum[s] += __shfl_xor_sync(0xffffffffu, rowsum[s], 1);
            rowsum[s] += __shfl_xor_sync(0xffffffffu, rowsum[s], 2);
        }
        if (t == 0){
            #pragma unroll
            for (int s=0;s<4;s++){
                int r = wm*32 + (s>>1)*16 + (s&1)*8 + g;
                atomicAdd(&rowsum_sm[r], rowsum[s]);
            }
        }
        __syncthreads();
        if (tid < TILE) atomicAdd(&g_rowsum[rt*TILE + tid], rowsum_sm[tid]);
        __syncthreads();
    }
}

// ---------------- final: loss = mean(log(rowsum) - Sv) ----------------
__global__ void loss_kernel(int nrows){
    __shared__ float red_sm[8];
    int i = blockIdx.x*blockDim.x + threadIdx.x;
    int lane = threadIdx.x & 31, wid = threadIdx.x >> 5;
    float v = 0.f;
    if (i < nrows) v = logf(g_rowsum[i]) - g_Sv[i];
    #pragma unroll
    for (int o=16;o;o>>=1) v += __shfl_xor_sync(0xffffffffu, v, o);
    if (lane == 0) red_sm[wid] = v;
    __syncthreads();
    if (threadIdx.x == 0){
        double s = 0.0;
        #pragma unroll
        for (int w=0;w<8;w++) s += (double)red_sm[w];
        atomicAdd(&g_acc, s);
    }
}

__global__ void finalize_kernel(float* __restrict__ out, int nrows){
    if (threadIdx.x==0 && blockIdx.x==0)
        out[0] = (float)(g_acc / (double)nrows);
}

extern "C" void kernel_launch(void* const* d_in, const int* in_sizes, int n_in,
                              void* d_out, int out_size){
    const float* X = (const float*)d_in[0];   // text_features
    const float* Y = (const float*)d_in[1];   // image_features
    float* out = (float*)d_out;
    int nrows = in_sizes[0] / DDIM;

    int nsm = 148;
    cudaDeviceGetAttribute(&nsm, cudaDevAttrMultiProcessorCount, 0);

    int nb = (nrows*32 + 255) / 256;
    norm_kernel<<<nb, 256>>>(X, 0, nrows);
    norm_kernel<<<nb, 256>>>(Y, 1, nrows);
    sv_kernel<<<nb, 256>>>(X, Y, nrows);

    int nTrow = nrows / TILE;                  // 128
    int nchunk = nTrow / CHUNK_T;              // 8
    if (nchunk < 1) nchunk = 1;
    int items = nTrow * nchunk;                // 1024

    cudaFuncSetAttribute(lit_main_kernel,
                         cudaFuncAttributeMaxDynamicSharedMemorySize, SMEM_BYTES);
    lit_main_kernel<<<nsm, NTHREADS, SMEM_BYTES>>>(nrows, items, nTrow);

    loss_kernel<<<(nrows + 255)/256, 256>>>(nrows);
    finalize_kernel<<<1, 32>>>(out, nrows);
}

// round 6
// speedup vs baseline: 1.1743x; 1.0490x over previous
#include <cuda_runtime.h>
#include <cuda_bf16.h>
#include <cuda_fp16.h>
#include <cstdint>
#include <cstddef>

#define NROWS_MAX 16384
#define DDIM 256            // K bytes per row (fp8)
#define TILE 128
#define ROWB 272            // padded smem row bytes -> conflict-free LDS/ldmatrix
#define TILE_SMEM (TILE*ROWB)          // 34816
#define SMEM_BYTES (4*TILE_SMEM)       // A + B0 + B1 + B2 = 139264
#define NTHREADS 512
#define CHUNK_T 16          // B tiles per work item

// f16x2 constants: exactly representable in f16
#define KH2 0x4D274D27u     // half2(20.609375)   ~ log2(e)/0.07
#define CH2 0xC49CC49Cu     // half2(-4.609375)   = OFF - Kh with OFF folded
// stored rowsum = true_rowsum * 2^(Ch + Kt), Kt = 20.60992915555662
// log correction = (20.60992915555662 - 4.609375) * ln2 = 11.09073901
#define LOG_CORR 11.09073901f

__device__ __align__(16) uint8_t g_Xq[(size_t)NROWS_MAX*DDIM];
__device__ __align__(16) uint8_t g_Yq[(size_t)NROWS_MAX*DDIM];
__device__ float  g_Sv[NROWS_MAX];
__device__ float  g_rowsum[NROWS_MAX];
__device__ double g_acc;

static __device__ __forceinline__ uint32_t su32(const void* p){
    return (uint32_t)__cvta_generic_to_shared(p);
}
static __device__ __forceinline__ void cp16(uint32_t dst, const void* src){
    asm volatile("cp.async.cg.shared.global [%0], [%1], 16;\n" :: "r"(dst), "l"(src));
}
static __device__ __forceinline__ void cp_commit(){
    asm volatile("cp.async.commit_group;\n");
}
template<int N> static __device__ __forceinline__ void cp_wait(){
    asm volatile("cp.async.wait_group %0;\n" :: "n"(N));
}
static __device__ __forceinline__ uint16_t cvt_e4m3x2(float hi, float lo){
    uint16_t r;
    asm("cvt.rn.satfinite.e4m3x2.f32 %0, %1, %2;" : "=h"(r) : "f"(hi), "f"(lo));
    return r;
}
static __device__ __forceinline__ void ldsm4(uint32_t (&r)[4], uint32_t addr){
    asm volatile("ldmatrix.sync.aligned.m8n8.x4.shared.b16 {%0,%1,%2,%3}, [%4];"
        : "=r"(r[0]),"=r"(r[1]),"=r"(r[2]),"=r"(r[3]) : "r"(addr));
}
// fp8 e4m3 MMA with f16 accumulator (2 regs D/C)
static __device__ __forceinline__ void mma_fp8h(uint32_t* c, const uint32_t* a, const uint32_t* b){
    asm volatile(
        "mma.sync.aligned.m16n8k32.row.col.f16.e4m3.e4m3.f16 "
        "{%0,%1}, {%2,%3,%4,%5}, {%6,%7}, {%0,%1};\n"
        : "+r"(c[0]),"+r"(c[1])
        : "r"(a[0]),"r"(a[1]),"r"(a[2]),"r"(a[3]), "r"(b[0]),"r"(b[1]));
}

// ---------------- normalize: fp32 row -> unit-norm e4m3 row ----------------
__global__ void norm_kernel(const float* __restrict__ in, int which, int nrows){
    int gw   = (blockIdx.x*blockDim.x + threadIdx.x) >> 5;
    int lane = threadIdx.x & 31;
    if (gw >= nrows) return;
    const float4* rp = reinterpret_cast<const float4*>(in) + (size_t)gw*(DDIM/4);
    float4 v0 = rp[lane*2 + 0];
    float4 v1 = rp[lane*2 + 1];
    float ss = v0.x*v0.x + v0.y*v0.y + v0.z*v0.z + v0.w*v0.w
             + v1.x*v1.x + v1.y*v1.y + v1.z*v1.z + v1.w*v1.w;
    #pragma unroll
    for (int o=16;o;o>>=1) ss += __shfl_xor_sync(0xffffffffu, ss, o);
    float inv = 1.0f / fmaxf(sqrtf(ss), 1e-12f);
    union { uint16_t q[4]; uint2 u; } pk;
    pk.q[0] = cvt_e4m3x2(v0.y*inv, v0.x*inv);
    pk.q[1] = cvt_e4m3x2(v0.w*inv, v0.z*inv);
    pk.q[2] = cvt_e4m3x2(v1.y*inv, v1.x*inv);
    pk.q[3] = cvt_e4m3x2(v1.w*inv, v1.z*inv);
    uint8_t* out = which ? g_Yq : g_Xq;
    *reinterpret_cast<uint2*>(out + (size_t)gw*DDIM + lane*8) = pk.u;
}

// ------------- Sv diagonal (fp32): (dot-1)/t ; zero rowsum + acc -------------
__global__ void sv_kernel(const float* __restrict__ X, const float* __restrict__ Y, int nrows){
    if (blockIdx.x==0 && threadIdx.x==0) g_acc = 0.0;
    int gw   = (blockIdx.x*blockDim.x + threadIdx.x) >> 5;
    int lane = threadIdx.x & 31;
    if (gw >= nrows) return;
    const float4* xp = reinterpret_cast<const float4*>(X) + (size_t)gw*(DDIM/4);
    const float4* yp = reinterpret_cast<const float4*>(Y) + (size_t)gw*(DDIM/4);
    float dot=0.f, ssx=0.f, ssy=0.f;
    #pragma unroll
    for (int j=0;j<2;j++){
        float4 x = xp[lane*2+j], y = yp[lane*2+j];
        dot += x.x*y.x + x.y*y.y + x.z*y.z + x.w*y.w;
        ssx += x.x*x.x + x.y*x.y + x.z*x.z + x.w*x.w;
        ssy += y.x*y.x + y.y*y.y + y.z*y.z + y.w*y.w;
    }
    #pragma unroll
    for (int o=16;o;o>>=1){
        dot += __shfl_xor_sync(0xffffffffu, dot, o);
        ssx += __shfl_xor_sync(0xffffffffu, ssx, o);
        ssy += __shfl_xor_sync(0xffffffffu, ssy, o);
    }
    if (lane==0){
        float d = dot / (fmaxf(sqrtf(ssx),1e-12f) * fmaxf(sqrtf(ssy),1e-12f));
        g_Sv[gw] = (d - 1.0f) * 14.285714285714286f;
        g_rowsum[gw] = 0.0f;
    }
}

// ---------------- main: persistent fused fp8 GEMM + exp2(f16x2) + row-sum ----------
__global__ void __launch_bounds__(NTHREADS, 1) lit_main_kernel(int nrows, int items, int nTrow){
    extern __shared__ char sm[];
    __shared__ float rowsum_sm[TILE];

    const int tid  = threadIdx.x;
    const int lane = tid & 31, wid = tid >> 5;
    const int wm = wid >> 2, wn = wid & 3;       // 4x4 warp grid over 128x128
    const int g = lane >> 2, t = lane & 3;

    const uint32_t sA = su32(sm);
    const uint32_t aoff = sA + (uint32_t)((wm*32 + (lane & 15))*ROWB + ((lane >> 4) & 1)*16);
    const uint32_t boff = (uint32_t)((wn*32 + (lane & 7) + ((lane >> 4) & 1)*8)*ROWB
                                     + ((lane >> 3) & 1)*16);

    for (int item = blockIdx.x; item < items; item += gridDim.x){
        const int rt = item % nTrow;          // row tile
        const int ch = item / nTrow;          // col chunk
        const int c0 = ch * CHUNK_T;

        if (tid < TILE) rowsum_sm[tid] = 0.f;

        // prologue: group0 = A + B0, group1 = B1
        {
            const uint8_t* Ag  = g_Xq + (size_t)rt*TILE*DDIM;
            const uint8_t* Yg0 = g_Yq + (size_t)c0*TILE*DDIM;
            #pragma unroll
            for (int j=0;j<4;j++){
                int idx = tid + NTHREADS*j;   // 2048 16B chunks
                int r = idx >> 4, c = idx & 15;
                cp16(sA + r*ROWB + c*16,             Ag  + r*DDIM + c*16);
                cp16(sA + TILE_SMEM + r*ROWB + c*16, Yg0 + r*DDIM + c*16);
            }
            cp_commit();
            #pragma unroll
            for (int j=0;j<4;j++){
                int idx = tid + NTHREADS*j;
                int r = idx >> 4, c = idx & 15;
                cp16(sA + 2*TILE_SMEM + r*ROWB + c*16, Yg0 + TILE*DDIM + r*DDIM + c*16);
            }
            cp_commit();
        }

        // acc[(mc*4+nc)*2 + d] : f16x2 accumulators (rows g / g+8, cols 2t,2t+1)
        uint32_t acc[16];
        #pragma unroll
        for (int j=0;j<16;j++) acc[j] = 0u;
        float rowsum[4] = {0.f,0.f,0.f,0.f};

        for (int it = 0; it < CHUNK_T; ++it){
            if (it + 2 < CHUNK_T){
                const uint8_t* Yg = g_Yq + (size_t)(c0 + it + 2)*TILE*DDIM;
                uint32_t bw = sA + (uint32_t)((1 + (it+2)%3)*TILE_SMEM);
                #pragma unroll
                for (int j=0;j<4;j++){
                    int idx = tid + NTHREADS*j;
                    int r = idx >> 4, c = idx & 15;
                    cp16(bw + r*ROWB + c*16, Yg + r*DDIM + c*16);
                }
            }
            cp_commit();            // uniform: one group per iteration
            cp_wait<2>();           // group for tile `it` complete
            __syncthreads();

            const uint32_t bb = sA + (uint32_t)((1 + it%3)*TILE_SMEM) + boff;

            #pragma unroll
            for (int ks=0; ks<8; ++ks){
                uint32_t a0[4], a1[4], b0[4], b1[4];
                ldsm4(a0, aoff + ks*32);
                ldsm4(a1, aoff + 16*ROWB + ks*32);
                ldsm4(b0, bb + ks*32);
                ldsm4(b1, bb + 16*ROWB + ks*32);
                mma_fp8h(acc + 0,  a0, b0 + 0);   // mc0 nc0
                mma_fp8h(acc + 2,  a0, b0 + 2);   // mc0 nc1
                mma_fp8h(acc + 4,  a0, b1 + 0);   // mc0 nc2
                mma_fp8h(acc + 6,  a0, b1 + 2);   // mc0 nc3
                mma_fp8h(acc + 8,  a1, b0 + 0);   // mc1 nc0
                mma_fp8h(acc + 10, a1, b0 + 2);
                mma_fp8h(acc + 12, a1, b1 + 0);
                mma_fp8h(acc + 14, a1, b1 + 2);
            }

            // epilogue: 2^(s*Kh + Ch) in f16x2, sum per (mc,d) slot, reset acc
            uint32_t sum2[4] = {0u,0u,0u,0u};
            #pragma unroll
            for (int j=0;j<16;j++){
                int slot = ((j >> 3) << 1) | (j & 1);   // mc*2 + d
                uint32_t e;
                asm("fma.rn.f16x2 %0, %1, %2, %3;" : "=r"(e)
                    : "r"(acc[j]), "r"(KH2), "r"(CH2));
                asm("ex2.approx.f16x2 %0, %1;" : "=r"(e) : "r"(e));
                asm("add.rn.f16x2 %0, %0, %1;" : "+r"(sum2[slot]) : "r"(e));
                acc[j] = 0u;
            }
            #pragma unroll
            for (int s=0;s<4;s++){
                __half2 h = *reinterpret_cast<__half2*>(&sum2[s]);
                rowsum[s] += __low2float(h) + __high2float(h);
            }
        }

        // merge: reduce over t lanes, then across wn warps via smem atomics
        #pragma unroll
        for (int s=0;s<4;s++){
            rowsum[s] += __shfl_xor_sync(0xffffffffu, rowsum[s], 1);
            rowsum[s] += __shfl_xor_sync(0xffffffffu, rowsum[s], 2);
        }
        if (t == 0){
            #pragma unroll
            for (int s=0;s<4;s++){
                int r = wm*32 + (s>>1)*16 + (s&1)*8 + g;
                atomicAdd(&rowsum_sm[r], rowsum[s]);
            }
        }
        __syncthreads();
        if (tid < TILE) atomicAdd(&g_rowsum[rt*TILE + tid], rowsum_sm[tid]);
        __syncthreads();
    }
}

// ---------------- final: loss = mean(log(rowsum) - corr - Sv) ----------------
__global__ void loss_kernel(int nrows){
    __shared__ float red_sm[8];
    int i = blockIdx.x*blockDim.x + threadIdx.x;
    int lane = threadIdx.x & 31, wid = threadIdx.x >> 5;
    float v = 0.f;
    if (i < nrows) v = logf(g_rowsum[i]) - LOG_CORR - g_Sv[i];
    #pragma unroll
    for (int o=16;o;o>>=1) v += __shfl_xor_sync(0xffffffffu, v, o);
    if (lane == 0) red_sm[wid] = v;
    __syncthreads();
    if (threadIdx.x == 0){
        double s = 0.0;
        #pragma unroll
        for (int w=0;w<8;w++) s += (double)red_sm[w];
        atomicAdd(&g_acc, s);
    }
}

__global__ void finalize_kernel(float* __restrict__ out, int nrows){
    if (threadIdx.x==0 && blockIdx.x==0)
        out[0] = (float)(g_acc / (double)nrows);
}

extern "C" void kernel_launch(void* const* d_in, const int* in_sizes, int n_in,
                              void* d_out, int out_size){
    const float* X = (const float*)d_in[0];   // text_features
    const float* Y = (const float*)d_in[1];   // image_features
    float* out = (float*)d_out;
    int nrows = in_sizes[0] / DDIM;

    int nsm = 148;
    cudaDeviceGetAttribute(&nsm, cudaDevAttrMultiProcessorCount, 0);

    int nb = (nrows*32 + 255) / 256;
    norm_kernel<<<nb, 256>>>(X, 0, nrows);
    norm_kernel<<<nb, 256>>>(Y, 1, nrows);
    sv_kernel<<<nb, 256>>>(X, Y, nrows);

    int nTrow = nrows / TILE;                  // 128
    int nchunk = nTrow / CHUNK_T;              // 8
    if (nchunk < 1) nchunk = 1;
    int items = nTrow * nchunk;                // 1024

    cudaFuncSetAttribute(lit_main_kernel,
                         cudaFuncAttributeMaxDynamicSharedMemorySize, SMEM_BYTES);
    lit_main_kernel<<<nsm, NTHREADS, SMEM_BYTES>>>(nrows, items, nTrow);

    loss_kernel<<<(nrows + 255)/256, 256>>>(nrows);
    finalize_kernel<<<1, 32>>>(out, nrows);
}

// round 9
// speedup vs baseline: 1.1982x; 1.0204x over previous
#include <cuda_runtime.h>
#include <cuda_bf16.h>
#include <cuda_fp16.h>
#include <cstdint>
#include <cstddef>

#define NROWS_MAX 16384
#define DDIM 256            // K bytes per row (fp8)
#define TILE 128
#define ROWB 272            // padded smem row bytes -> conflict-free LDS/ldmatrix
#define TILE_SMEM (TILE*ROWB)          // 34816
#define SMEM_BYTES (4*TILE_SMEM)       // A + B0 + B1 + B2 = 139264
#define NTHREADS 512
#define CHUNK_T 16          // B tiles per work item (even!)

// f16x2 constants: exactly representable in f16
#define KH2 0x4D274D27u     // half2(20.609375)   ~ log2(e)/0.07
#define CH2 0xC49CC49Cu     // half2(-4.609375)   offset folded for f16 range
// stored rowsum = true_rowsum * 2^(Ch + Kt), Kt = 20.60992915555662
#define LOG_CORR 11.09073901f   // (20.60992915555662 - 4.609375) * ln2

__device__ __align__(16) uint8_t g_Xq[(size_t)NROWS_MAX*DDIM];
__device__ __align__(16) uint8_t g_Yq[(size_t)NROWS_MAX*DDIM];
__device__ float  g_Sv[NROWS_MAX];
__device__ float  g_rowsum[NROWS_MAX];
__device__ double g_acc;

static __device__ __forceinline__ uint32_t su32(const void* p){
    return (uint32_t)__cvta_generic_to_shared(p);
}
static __device__ __forceinline__ void cp16(uint32_t dst, const void* src){
    asm volatile("cp.async.cg.shared.global [%0], [%1], 16;\n" :: "r"(dst), "l"(src));
}
static __device__ __forceinline__ void cp_commit(){
    asm volatile("cp.async.commit_group;\n");
}
template<int N> static __device__ __forceinline__ void cp_wait(){
    asm volatile("cp.async.wait_group %0;\n" :: "n"(N));
}
static __device__ __forceinline__ uint16_t cvt_e4m3x2(float hi, float lo){
    uint16_t r;
    asm("cvt.rn.satfinite.e4m3x2.f32 %0, %1, %2;" : "=h"(r) : "f"(hi), "f"(lo));
    return r;
}
static __device__ __forceinline__ void ldsm4(uint32_t (&r)[4], uint32_t addr){
    asm volatile("ldmatrix.sync.aligned.m8n8.x4.shared.b16 {%0,%1,%2,%3}, [%4];"
        : "=r"(r[0]),"=r"(r[1]),"=r"(r[2]),"=r"(r[3]) : "r"(addr));
}
// fp8 e4m3 MMA with f16 accumulator (2 regs D/C)
static __device__ __forceinline__ void mma_fp8h(uint32_t* c, const uint32_t* a, const uint32_t* b){
    asm volatile(
        "mma.sync.aligned.m16n8k32.row.col.f16.e4m3.e4m3.f16 "
        "{%0,%1}, {%2,%3,%4,%5}, {%6,%7}, {%0,%1};\n"
        : "+r"(c[0]),"+r"(c[1])
        : "r"(a[0]),"r"(a[1]),"r"(a[2]),"r"(a[3]), "r"(b[0]),"r"(b[1]));
}
// epilogue triple for one f16x2 element: e = 2^(v*Kh+Ch); sum += e; v = 0
static __device__ __forceinline__ void epi_elem(uint32_t& v, uint32_t& sum){
    uint32_t e;
    asm("fma.rn.f16x2 %0, %1, %2, %3;" : "=r"(e) : "r"(v), "r"(KH2), "r"(CH2));
    asm("ex2.approx.f16x2 %0, %1;" : "=r"(e) : "r"(e));
    asm("add.rn.f16x2 %0, %0, %1;" : "+r"(sum) : "r"(e));
    v = 0u;
}

// ---------------- normalize: fp32 row -> unit-norm e4m3 row ----------------
__global__ void norm_kernel(const float* __restrict__ in, int which, int nrows){
    int gw   = (blockIdx.x*blockDim.x + threadIdx.x) >> 5;
    int lane = threadIdx.x & 31;
    if (gw >= nrows) return;
    const float4* rp = reinterpret_cast<const float4*>(in) + (size_t)gw*(DDIM/4);
    float4 v0 = rp[lane*2 + 0];
    float4 v1 = rp[lane*2 + 1];
    float ss = v0.x*v0.x + v0.y*v0.y + v0.z*v0.z + v0.w*v0.w
             + v1.x*v1.x + v1.y*v1.y + v1.z*v1.z + v1.w*v1.w;
    #pragma unroll
    for (int o=16;o;o>>=1) ss += __shfl_xor_sync(0xffffffffu, ss, o);
    float inv = 1.0f / fmaxf(sqrtf(ss), 1e-12f);
    union { uint16_t q[4]; uint2 u; } pk;
    pk.q[0] = cvt_e4m3x2(v0.y*inv, v0.x*inv);
    pk.q[1] = cvt_e4m3x2(v0.w*inv, v0.z*inv);
    pk.q[2] = cvt_e4m3x2(v1.y*inv, v1.x*inv);
    pk.q[3] = cvt_e4m3x2(v1.w*inv, v1.z*inv);
    uint8_t* out = which ? g_Yq : g_Xq;
    *reinterpret_cast<uint2*>(out + (size_t)gw*DDIM + lane*8) = pk.u;
}

// ------------- Sv diagonal (fp32): (dot-1)/t ; zero rowsum + acc -------------
__global__ void sv_kernel(const float* __restrict__ X, const float* __restrict__ Y, int nrows){
    if (blockIdx.x==0 && threadIdx.x==0) g_acc = 0.0;
    int gw   = (blockIdx.x*blockDim.x + threadIdx.x) >> 5;
    int lane = threadIdx.x & 31;
    if (gw >= nrows) return;
    const float4* xp = reinterpret_cast<const float4*>(X) + (size_t)gw*(DDIM/4);
    const float4* yp = reinterpret_cast<const float4*>(Y) + (size_t)gw*(DDIM/4);
    float dot=0.f, ssx=0.f, ssy=0.f;
    #pragma unroll
    for (int j=0;j<2;j++){
        float4 x = xp[lane*2+j], y = yp[lane*2+j];
        dot += x.x*y.x + x.y*y.y + x.z*y.z + x.w*y.w;
        ssx += x.x*x.x + x.y*x.y + x.z*x.z + x.w*x.w;
        ssy += y.x*y.x + y.y*y.y + y.z*y.z + y.w*y.w;
    }
    #pragma unroll
    for (int o=16;o;o>>=1){
        dot += __shfl_xor_sync(0xffffffffu, dot, o);
        ssx += __shfl_xor_sync(0xffffffffu, ssx, o);
        ssy += __shfl_xor_sync(0xffffffffu, ssy, o);
    }
    if (lane==0){
        float d = dot / (fmaxf(sqrtf(ssx),1e-12f) * fmaxf(sqrtf(ssy),1e-12f));
        g_Sv[gw] = (d - 1.0f) * 14.285714285714286f;
        g_rowsum[gw] = 0.0f;
    }
}

// one tile iteration. Sound pipeline:
//   sync (end prior reads) -> prefetch it+2 -> commit -> wait own groups ->
//   sync (visibility of ALL warps' cp.async) -> mma (+ interleaved epilogue of prv)
static __device__ __forceinline__ void tile_body(
    int it, bool doEpi, uint32_t sA, const uint8_t* Ychunk,
    uint32_t aoff, uint32_t boff, int tid,
    uint32_t (&cur)[16], uint32_t (&prv)[16], float (&rowsum)[4])
{
    __syncthreads();   // all warps done reading buffer (it-1)%3 == (it+2)%3

    if (it + 2 < CHUNK_T){
        const uint8_t* Yg = Ychunk + (size_t)(it + 2)*TILE*DDIM;
        uint32_t bw = sA + (uint32_t)((1 + (it+2)%3)*TILE_SMEM);
        #pragma unroll
        for (int j=0;j<4;j++){
            int idx = tid + NTHREADS*j;
            int r = idx >> 4, c = idx & 15;
            cp16(bw + r*ROWB + c*16, Yg + r*DDIM + c*16);
        }
    }
    cp_commit();            // uniform: one group per iteration
    cp_wait<2>();           // this thread's group for tile `it` complete
    __syncthreads();        // ALL warps' cp.async for tile `it` now visible

    const uint32_t bb = sA + (uint32_t)((1 + it%3)*TILE_SMEM) + boff;

    uint32_t sum2[4] = {0u,0u,0u,0u};
    #pragma unroll
    for (int ks=0; ks<8; ++ks){
        uint32_t a0[4], a1[4], b0[4], b1[4];
        ldsm4(a0, aoff + ks*32);
        ldsm4(a1, aoff + 16*ROWB + ks*32);
        ldsm4(b0, bb + ks*32);
        ldsm4(b1, bb + 16*ROWB + ks*32);
        mma_fp8h(cur + 0,  a0, b0 + 0);
        mma_fp8h(cur + 2,  a0, b0 + 2);
        mma_fp8h(cur + 4,  a0, b1 + 0);
        mma_fp8h(cur + 6,  a0, b1 + 2);
        mma_fp8h(cur + 8,  a1, b0 + 0);
        mma_fp8h(cur + 10, a1, b0 + 2);
        mma_fp8h(cur + 12, a1, b1 + 0);
        mma_fp8h(cur + 14, a1, b1 + 2);
        if (doEpi){
            // 2 elements of prev tile per k-step: MUFU/FMA co-issue with tensor
            int j = ks*2;
            int s0 = ((j    >> 3) << 1) | (j & 1);
            int s1 = (((j+1)>> 3) << 1) | ((j+1) & 1);
            epi_elem(prv[j],   sum2[s0]);
            epi_elem(prv[j+1], sum2[s1]);
        }
    }
    if (doEpi){
        #pragma unroll
        for (int s=0;s<4;s++){
            __half2 h = *reinterpret_cast<__half2*>(&sum2[s]);
            rowsum[s] += __low2float(h) + __high2float(h);
        }
    }
}

// ---------------- main: persistent fused fp8 GEMM + exp2(f16x2) + row-sum ----------
__global__ void __launch_bounds__(NTHREADS, 1) lit_main_kernel(int nrows, int items, int nTrow){
    extern __shared__ char sm[];
    __shared__ float rowsum_sm[TILE];

    const int tid  = threadIdx.x;
    const int lane = tid & 31, wid = tid >> 5;
    const int wm = wid >> 2, wn = wid & 3;       // 4x4 warp grid over 128x128
    const int g = lane >> 2, t = lane & 3;

    const uint32_t sA = su32(sm);
    const uint32_t aoff = sA + (uint32_t)((wm*32 + (lane & 15))*ROWB + ((lane >> 4) & 1)*16);
    const uint32_t boff = (uint32_t)((wn*32 + (lane & 7) + ((lane >> 4) & 1)*8)*ROWB
                                     + ((lane >> 3) & 1)*16);

    for (int item = blockIdx.x; item < items; item += gridDim.x){
        const int rt = item % nTrow;          // row tile
        const int ch = item / nTrow;          // col chunk
        const uint8_t* Ychunk = g_Yq + (size_t)(ch * CHUNK_T)*TILE*DDIM;

        if (tid < TILE) rowsum_sm[tid] = 0.f;

        // prologue: group0 = A + B0, group1 = B1
        {
            const uint8_t* Ag  = g_Xq + (size_t)rt*TILE*DDIM;
            #pragma unroll
            for (int j=0;j<4;j++){
                int idx = tid + NTHREADS*j;   // 2048 16B chunks
                int r = idx >> 4, c = idx & 15;
                cp16(sA + r*ROWB + c*16,             Ag     + r*DDIM + c*16);
                cp16(sA + TILE_SMEM + r*ROWB + c*16, Ychunk + r*DDIM + c*16);
            }
            cp_commit();
            #pragma unroll
            for (int j=0;j<4;j++){
                int idx = tid + NTHREADS*j;
                int r = idx >> 4, c = idx & 15;
                cp16(sA + 2*TILE_SMEM + r*ROWB + c*16, Ychunk + TILE*DDIM + r*DDIM + c*16);
            }
            cp_commit();
        }

        uint32_t acc0[16], acc1[16];
        #pragma unroll
        for (int j=0;j<16;j++){ acc0[j] = 0u; acc1[j] = 0u; }
        float rowsum[4] = {0.f,0.f,0.f,0.f};

        // schedule: tile it epilogues tile it-1 (opposite acc), which also resets it
        tile_body(0, false, sA, Ychunk, aoff, boff, tid, acc0, acc1, rowsum);
        for (int it = 1; it + 1 < CHUNK_T; it += 2){
            tile_body(it,   true, sA, Ychunk, aoff, boff, tid, acc1, acc0, rowsum);
            tile_body(it+1, true, sA, Ychunk, aoff, boff, tid, acc0, acc1, rowsum);
        }
        tile_body(CHUNK_T-1, true, sA, Ychunk, aoff, boff, tid, acc1, acc0, rowsum);
        // drain: last tile (CHUNK_T-1) lives in acc1
        {
            uint32_t sum2[4] = {0u,0u,0u,0u};
            #pragma unroll
            for (int j=0;j<16;j++){
                int s = ((j >> 3) << 1) | (j & 1);
                epi_elem(acc1[j], sum2[s]);
            }
            #pragma unroll
            for (int s=0;s<4;s++){
                __half2 h = *reinterpret_cast<__half2*>(&sum2[s]);
                rowsum[s] += __low2float(h) + __high2float(h);
            }
        }

        // merge: reduce over t lanes, then across wn warps via smem atomics
        #pragma unroll
        for (int s=0;s<4;s++){
            rowsum[s] += __shfl_xor_sync(0xffffffffu, rowsum[s], 1);
            rowsum[s] += __shfl_xor_sync(0xffffffffu, rowsum[s], 2);
        }
        if (t == 0){
            #pragma unroll
            for (int s=0;s<4;s++){
                int r = wm*32 + (s>>1)*16 + (s&1)*8 + g;
                atomicAdd(&rowsum_sm[r], rowsum[s]);
            }
        }
        __syncthreads();
        if (tid < TILE) atomicAdd(&g_rowsum[rt*TILE + tid], rowsum_sm[tid]);
        __syncthreads();
    }
}

// ---------------- final: loss = mean(log(rowsum) - corr - Sv) ----------------
__global__ void loss_kernel(int nrows){
    __shared__ float red_sm[8];
    int i = blockIdx.x*blockDim.x + threadIdx.x;
    int lane = threadIdx.x & 31, wid = threadIdx.x >> 5;
    float v = 0.f;
    if (i < nrows) v = logf(g_rowsum[i]) - LOG_CORR - g_Sv[i];
    #pragma unroll
    for (int o=16;o;o>>=1) v += __shfl_xor_sync(0xffffffffu, v, o);
    if (lane == 0) red_sm[wid] = v;
    __syncthreads();
    if (threadIdx.x == 0){
        double s = 0.0;
        #pragma unroll
        for (int w=0;w<8;w++) s += (double)red_sm[w];
        atomicAdd(&g_acc, s);
    }
}

__global__ void finalize_kernel(float* __restrict__ out, int nrows){
    if (threadIdx.x==0 && blockIdx.x==0)
        out[0] = (float)(g_acc / (double)nrows);
}

extern "C" void kernel_launch(void* const* d_in, const int* in_sizes, int n_in,
                              void* d_out, int out_size){
    const float* X = (const float*)d_in[0];   // text_features
    const float* Y = (const float*)d_in[1];   // image_features
    float* out = (float*)d_out;
    int nrows = in_sizes[0] / DDIM;

    int nsm = 148;
    cudaDeviceGetAttribute(&nsm, cudaDevAttrMultiProcessorCount, 0);

    int nb = (nrows*32 + 255) / 256;
    norm_kernel<<<nb, 256>>>(X, 0, nrows);
    norm_kernel<<<nb, 256>>>(Y, 1, nrows);
    sv_kernel<<<nb, 256>>>(X, Y, nrows);

    int nTrow = nrows / TILE;                  // 128
    int nchunk = nTrow / CHUNK_T;              // 8
    if (nchunk < 1) nchunk = 1;
    int items = nTrow * nchunk;                // 1024

    cudaFuncSetAttribute(lit_main_kernel,
                         cudaFuncAttributeMaxDynamicSharedMemorySize, SMEM_BYTES);
    lit_main_kernel<<<nsm, NTHREADS, SMEM_BYTES>>>(nrows, items, nTrow);

    loss_kernel<<<(nrows + 255)/256, 256>>>(nrows);
    finalize_kernel<<<1, 32>>>(out, nrows);
}